// round 1
// baseline (speedup 1.0000x reference)
#include <cuda_runtime.h>
#include <cuda_bf16.h>

// DAS beamforming: out[b,z,x,k] = sum_c interp(rf[b,c,:,k], s(b,c,z,x))
// Shapes fixed by the problem instance.
#define BB 2
#define NC 128
#define NS 2048
#define NZ 256
#define NX 256
#define KK 4
#define MM (NZ * NX)

#define THREADS 256

__global__ __launch_bounds__(THREADS) void das_kernel(
    const float* __restrict__ rf,   // [B, NC, NS, K]
    const float* __restrict__ g,    // [B, NZ, NX, 3]
    const float* __restrict__ pr,   // [B, NC, 3]
    const float* __restrict__ p,    // [B, 4]
    float* __restrict__ out)        // [B, NZ, NX, K]
{
    __shared__ float4 s_pr[NC];     // padded receiver positions (broadcast-friendly)
    __shared__ float s_scale, s_base;

    const int b = blockIdx.y;
    const int m = blockIdx.x * THREADS + threadIdx.x;   // pixel index within image

    // Stage receiver positions for this batch into SMEM (one float4 per channel).
    if (threadIdx.x < NC) {
        const float* q = pr + ((size_t)b * NC + threadIdx.x) * 3;
        s_pr[threadIdx.x] = make_float4(q[0], q[1], q[2], 0.0f);
    }
    if (threadIdx.x == 0) {
        const float c0 = p[b * 4 + 0];
        const float fs = p[b * 4 + 1];
        const float t0 = p[b * 4 + 2];
        s_scale = fs / c0;            // samples per meter
        s_base  = fs * t0 / c0;       // sample offset from t0
    }
    __syncthreads();

    // Pixel coordinates (g is [.,.,.,3], 12B stride — three coalesced-ish loads).
    const float* gp = g + ((size_t)b * MM + m) * 3;
    const float gx = gp[0];
    const float gy = gp[1];
    const float gz = gp[2];          // d_tx = depth coordinate

    const float scale = s_scale;
    const float base  = s_base;

    // rf viewed as float4 rows: rf4[(b*NC + c)*NS + i] == rf[b,c,i,0:4]
    const float4* __restrict__ rf4 = (const float4*)rf + (size_t)b * NC * NS;

    float ax = 0.0f, ay = 0.0f, az = 0.0f, aw = 0.0f;

    #pragma unroll 4
    for (int c = 0; c < NC; ++c) {
        const float4 pc = s_pr[c];
        const float dx = gx - pc.x;
        const float dy = gy - pc.y;
        const float dz = gz - pc.z;
        const float r2 = fmaf(dx, dx, fmaf(dy, dy, dz * dz));
        float drx;
        asm("sqrt.approx.f32 %0, %1;" : "=f"(drx) : "f"(r2));

        // fractional sample index, clamped per reference semantics
        float s = fmaf(scale, drx + gz, base);
        s = fminf(fmaxf(s, 0.0f), (float)(NS - 1));
        const float i0f = fminf(floorf(s), (float)(NS - 2));
        const int   i0  = (int)i0f;
        const float w   = s - i0f;
        const float wm  = 1.0f - w;

        const float4* ptr = rf4 + (size_t)c * NS + i0;
        const float4 y0 = ptr[0];
        const float4 y1 = ptr[1];

        ax = fmaf(wm, y0.x, fmaf(w, y1.x, ax));
        ay = fmaf(wm, y0.y, fmaf(w, y1.y, ay));
        az = fmaf(wm, y0.z, fmaf(w, y1.z, az));
        aw = fmaf(wm, y0.w, fmaf(w, y1.w, aw));
    }

    ((float4*)out)[(size_t)b * MM + m] = make_float4(ax, ay, az, aw);
}

extern "C" void kernel_launch(void* const* d_in, const int* in_sizes, int n_in,
                              void* d_out, int out_size) {
    const float* rf = (const float*)d_in[0];
    const float* g  = (const float*)d_in[1];
    const float* pr = (const float*)d_in[2];
    const float* p  = (const float*)d_in[3];
    float* out = (float*)d_out;

    dim3 grid(MM / THREADS, BB);
    das_kernel<<<grid, THREADS>>>(rf, g, pr, p, out);
}